// round 16
// baseline (speedup 1.0000x reference)
#include <cuda_runtime.h>
#include <math.h>

#define BB 4
#define NN 512
#define HD 64
#define IDM 128
#define PI_F 3.14159265358979323846f
#define INV_SQRT2 0.70710678118654752440f
#define RPB 8            // rows per prep block

// tanh-based erf approx: erf(d) ~= tanh(C0*d + C1*d^3)
#define ERF_C0 1.1283791671f
#define ERF_C1 0.1009052923f

// Scratch (device globals: no allocation allowed)
__device__ __align__(16) float g_U2[BB*NN*IDM];   // (A@We1 + be1) / sqrt2
__device__ __align__(16) float g_V2[BB*NN*IDM];   // (C@We1)       / sqrt2
__device__ float g_SU[BB*NN];                     // 0.5 * dot(U, w2)
__device__ float g_SV[BB*NN];

typedef unsigned long long u64;

__device__ __forceinline__ u64 pack2(float lo, float hi) {
    u64 r; asm("mov.b64 %0, {%1, %2};" : "=l"(r) : "f"(lo), "f"(hi)); return r;
}
__device__ __forceinline__ void unpack2(u64 v, float& lo, float& hi) {
    asm("mov.b64 {%0, %1}, %2;" : "=f"(lo), "=f"(hi) : "l"(v));
}
__device__ __forceinline__ u64 fma2(u64 a, u64 b, u64 c) {
    u64 r; asm("fma.rn.f32x2 %0, %1, %2, %3;" : "=l"(r) : "l"(a), "l"(b), "l"(c)); return r;
}
__device__ __forceinline__ u64 add2(u64 a, u64 b) {
    u64 r; asm("add.rn.f32x2 %0, %1, %2;" : "=l"(r) : "l"(a), "l"(b)); return r;
}
__device__ __forceinline__ u64 mul2(u64 a, u64 b) {
    u64 r; asm("mul.rn.f32x2 %0, %1, %2;" : "=l"(r) : "l"(a), "l"(b)); return r;
}
__device__ __forceinline__ float fast_tanh(float x) {
    float y; asm("tanh.approx.f32 %0, %1;" : "=f"(y) : "f"(x)); return y;
}

// ---------------------------------------------------------------------------
// Precompute. Grid 256, 128 thr, 8 rows/block. Unroll-8 in phases 2/3 for MLP.
// ---------------------------------------------------------------------------
__global__ __launch_bounds__(128) void prep_kernel(
    const float* __restrict__ bf,   const float* __restrict__ emb,
    const float* __restrict__ Wcls, const float* __restrict__ bcls,
    const float* __restrict__ Wpos, const float* __restrict__ bpos,
    const float* __restrict__ Win,  const float* __restrict__ bin,
    const float* __restrict__ Wout, const float* __restrict__ bout,
    const float* __restrict__ We1,  const float* __restrict__ be1,
    const float* __restrict__ We2)
{
    int t = threadIdx.x, lane = t & 31, wid = t >> 5;
    int row0 = blockIdx.x * RPB;

    __shared__ __align__(16) float xs[RPB][HD];
    __shared__ __align__(16) float featsT[HD][RPB];   // k-major
    __shared__ __align__(16) float ApreT[IDM][RPB];   // k-major
    __shared__ __align__(16) float BpreT[IDM][RPB];
    __shared__ float p0s[RPB], p1s[RPB];
    __shared__ float partU[4][RPB], partV[4][RPB];

    for (int idx = t; idx < RPB*HD; idx += 128)
        ((float*)xs)[idx] = bf[row0*HD + idx];

    if (t < RPB) {
        int row = row0 + t;
        float ang = emb[row*2 + 0] * PI_F;
        float rho = emb[row*2 + 1] * 800.0f;
        float tn = tanf(ang);
        float ic = 1.0f / cosf(ang);
        float lin1 = (1.0f - 1e-5f) / 71.0f;
        float y0 = 160.0f;
        float y1 = 160.0f - lin1 * 320.0f;
        p0s[t] = (-tn * y0 + rho * ic) * (1.0f / 800.0f);
        p1s[t] = (-tn * y1 + rho * ic) * (1.0f / 800.0f);
    }
    __syncthreads();

    // phase 1: feats = relu(x @ Wcls + bcls), two rows per pass
    {
        int rhalf = t >> 6, d = t & 63;
        float bc = bcls[d];
        #pragma unroll
        for (int pass = 0; pass < RPB; pass += 2) {
            int r = pass + rhalf;
            float acc = bc;
            #pragma unroll 8
            for (int k = 0; k < HD; k++) acc = fmaf(xs[r][k], Wcls[k*HD + d], acc);
            featsT[d][r] = fmaxf(acc, 0.0f);
        }
    }
    __syncthreads();

    // phase 2: f_in / f_out for all 8 rows (f32x2 packed, unroll 8)
    {
        float bi = bin[t], bo = bout[t];
        u64 ai01 = pack2(bi,bi), ai23 = ai01, ai45 = ai01, ai67 = ai01;
        u64 ao01 = pack2(bo,bo), ao23 = ao01, ao45 = ao01, ao67 = ao01;
        #pragma unroll 8
        for (int k = 0; k < HD; k++) {
            float win  = Win [k*IDM + t];
            float wout = Wout[k*IDM + t];
            u64 wi = pack2(win, win), wo = pack2(wout, wout);
            const ulonglong2* fp = (const ulonglong2*)&featsT[k][0];
            ulonglong2 fA = fp[0], fB = fp[1];
            ai01 = fma2(fA.x, wi, ai01);  ao01 = fma2(fA.x, wo, ao01);
            ai23 = fma2(fA.y, wi, ai23);  ao23 = fma2(fA.y, wo, ao23);
            ai45 = fma2(fB.x, wi, ai45);  ao45 = fma2(fB.x, wo, ao45);
            ai67 = fma2(fB.y, wi, ai67);  ao67 = fma2(fB.y, wo, ao67);
        }
        float wp0 = Wpos[t], wp1 = Wpos[IDM + t], bp = bpos[t];
        float pe[RPB];
        #pragma unroll
        for (int r = 0; r < RPB; r++) pe[r] = fmaf(p0s[r], wp0, p1s[r] * wp1);
        u64 bp2  = pack2(bp, bp);
        u64 pe01 = pack2(pe[0], pe[1]), pe23 = pack2(pe[2], pe[3]);
        u64 pe45 = pack2(pe[4], pe[5]), pe67 = pack2(pe[6], pe[7]);
        u64* arow = (u64*)&ApreT[t][0];
        u64* brow = (u64*)&BpreT[t][0];
        arow[0] = add2(ai01, add2(pe01, bp2));
        arow[1] = add2(ai23, add2(pe23, bp2));
        arow[2] = add2(ai45, add2(pe45, bp2));
        arow[3] = add2(ai67, add2(pe67, bp2));
        brow[0] = add2(ao01, pe01);
        brow[1] = add2(ao23, pe23);
        brow[2] = add2(ao45, pe45);
        brow[3] = add2(ao67, pe67);
    }
    __syncthreads();

    // phase 3: U = Apre @ We1 + be1, V = Bpre @ We1 (f32x2 packed, unroll 8)
    float uu[RPB], vv[RPB];
    {
        float b1 = be1[t];
        u64 u01 = pack2(b1,b1), u23 = u01, u45 = u01, u67 = u01;
        u64 v01 = 0ULL, v23 = 0ULL, v45 = 0ULL, v67 = 0ULL;
        #pragma unroll 8
        for (int k = 0; k < IDM; k++) {
            float w = We1[k*IDM + t];
            u64 w2 = pack2(w, w);
            const ulonglong2* ap = (const ulonglong2*)&ApreT[k][0];
            const ulonglong2* cp = (const ulonglong2*)&BpreT[k][0];
            ulonglong2 aA = ap[0], aB = ap[1];
            ulonglong2 cA = cp[0], cB = cp[1];
            u01 = fma2(aA.x, w2, u01);  v01 = fma2(cA.x, w2, v01);
            u23 = fma2(aA.y, w2, u23);  v23 = fma2(cA.y, w2, v23);
            u45 = fma2(aB.x, w2, u45);  v45 = fma2(cB.x, w2, v45);
            u67 = fma2(aB.y, w2, u67);  v67 = fma2(cB.y, w2, v67);
        }
        u64 is2 = pack2(INV_SQRT2, INV_SQRT2);
        u01 = mul2(u01, is2); u23 = mul2(u23, is2);
        u45 = mul2(u45, is2); u67 = mul2(u67, is2);
        v01 = mul2(v01, is2); v23 = mul2(v23, is2);
        v45 = mul2(v45, is2); v67 = mul2(v67, is2);
        unpack2(u01, uu[0], uu[1]); unpack2(u23, uu[2], uu[3]);
        unpack2(u45, uu[4], uu[5]); unpack2(u67, uu[6], uu[7]);
        unpack2(v01, vv[0], vv[1]); unpack2(v23, vv[2], vv[3]);
        unpack2(v45, vv[4], vv[5]); unpack2(v67, vv[6], vv[7]);
    }

    float w2s = We2[t] * INV_SQRT2;
    #pragma unroll
    for (int r = 0; r < RPB; r++) {
        g_U2[(row0 + r)*IDM + t] = uu[r];
        g_V2[(row0 + r)*IDM + t] = vv[r];
        float su = uu[r] * w2s, sv = vv[r] * w2s;
        #pragma unroll
        for (int o = 16; o; o >>= 1) {
            su += __shfl_xor_sync(0xffffffffu, su, o);
            sv += __shfl_xor_sync(0xffffffffu, sv, o);
        }
        if (lane == 0) { partU[wid][r] = su; partV[wid][r] = sv; }
    }
    __syncthreads();
    if (t < RPB)
        g_SU[row0 + t] = partU[0][t] + partU[1][t] + partU[2][t] + partU[3][t];
    else if (t < 2*RPB) {
        int r = t - RPB;
        g_SV[row0 + r] = partV[0][r] + partV[1][r] + partV[2][r] + partV[3][r];
    }
}

// ---------------------------------------------------------------------------
// Main: grid 1024 (exactly one wave at 7 blocks/SM), TWO columns per block:
// g = blockIdx and g + 1024 (same j, batch +2 — independent load draws).
// PDL: first column's list build overlaps prep; grid-dependency sync before
// touching prep outputs. Merged block list, warp-interleaved consumption,
// batch-4 register double-buffer, 6-shuffle segmented reduce.
// ---------------------------------------------------------------------------
__global__ __launch_bounds__(128, 7) void main_kernel(
    const float* __restrict__ cls, const int* __restrict__ aid,
    const float* __restrict__ emb,
    const float* __restrict__ We2, const float* __restrict__ be2,
    const float* __restrict__ Wn1, const float* __restrict__ bn1,
    const float* __restrict__ Wn2, const float* __restrict__ bn2,
    const float* __restrict__ Wh,  const float* __restrict__ bh,
    float* __restrict__ out)
{
    __shared__ unsigned short seg_s[4][128];
    __shared__ unsigned short lst_s[NN];
    __shared__ int cnt_s[4];
    __shared__ float pmax_s[4];
    __shared__ float n1_s[HD];

    int t = threadIdx.x, lane = t & 31, w = t >> 5;
    // entry-lane mapping for the 4-sum segmented reduce: e = bit3 + 2*bit4
    int elane = ((lane >> 3) & 1) | (((lane >> 4) & 1) << 1);
    bool hi4 = lane & 16, hi3 = lane & 8;

    #pragma unroll 1
    for (int pc = 0; pc < 2; pc++) {
        int g = blockIdx.x + pc*1024;
        int b = g >> 9;
        float cj = __ldg(&cls[g]);
        bool alive = (cj >= 0.4f);     // sigmoid(-1e6) == 0 in f32

        int cnt = 0;
        if (alive) {
            float aj  = __ldg(&emb[2*g]) * PI_F;
            int   idj = __ldg(&aid[g]);
            // per-warp segment list over i in [128w, 128w+128)
            int cntw = 0;
            {
                unsigned short* seg = seg_s[w];
                int gbase = b*NN + 128*w;
                #pragma unroll
                for (int c = 0; c < 128; c += 32) {
                    int gi = gbase + c + lane;
                    float ci = __ldg(&cls[gi]);
                    float ai = __ldg(&emb[2*gi]) * PI_F;
                    int  idi = __ldg(&aid[gi]);
                    bool p = (fabsf(ai - aj) < 0.5f) &&
                             ((ci > cj) || ((ci == cj) && (idi > idj)));
                    unsigned m = __ballot_sync(0xffffffffu, p);
                    if (p) seg[cntw + __popc(m & ((1u << lane) - 1u))]
                               = (unsigned short)(128*w + c + lane);
                    cntw += __popc(m);
                }
                if (lane == 0) cnt_s[w] = cntw;
            }
            __syncthreads();
            // merge segments into one contiguous block list
            int c0 = cnt_s[0], c1 = cnt_s[1], c2 = cnt_s[2], c3 = cnt_s[3];
            cnt = c0 + c1 + c2 + c3;
            {
                int off = (w > 0 ? c0 : 0) + (w > 1 ? c1 : 0) + (w > 2 ? c2 : 0);
                for (int k = lane; k < cntw; k += 32) lst_s[off + k] = seg_s[w][k];
            }
        }

        // wait for prep outputs (first pass only; overlapped list build above)
#if __CUDA_ARCH__ >= 900
        if (pc == 0) cudaGridDependencySynchronize();
#endif

        if (!alive) {
            if (t == 0) out[g] = 0.0f;
            __syncthreads();
            continue;
        }
        __syncthreads();   // lst_s merge visible

        // per-column constants
        const float* gSUb = g_SU + b*NN;
        ulonglong2 vp = *(const ulonglong2*)(g_V2 + (size_t)g*IDM + lane*4);
        float4 w2r = *(const float4*)(We2 + lane*4);
        float nvx, nvy, nvz, nvw;
        unpack2(vp.x, nvx, nvy); unpack2(vp.y, nvz, nvw);
        u64 nv01 = pack2(-nvx, -nvy), nv23 = pack2(-nvz, -nvw);
        u64 w01 = pack2(w2r.x*INV_SQRT2, w2r.y*INV_SQRT2);
        u64 w23 = pack2(w2r.z*INV_SQRT2, w2r.w*INV_SQRT2);
        u64 C0_2 = pack2(ERF_C0, ERF_C0), C1_2 = pack2(ERF_C1, ERF_C1);
        float cconst = __ldg(&be2[0]) - __ldg(&g_SV[g]);

        const float* Ub = g_U2 + (size_t)b*NN*IDM + lane*4;
        const unsigned short* lst = lst_s;

        float runmax = 0.0f;           // diagonal guarantees a 0 entry
        if (4*w < cnt) {
            // warp w consumes batches base = 4w, 4w+16, 4w+32, ...
            ulonglong2 UP[4];
            float su_p;
            #pragma unroll
            for (int e = 0; e < 4; e++) {
                int idx = lst[min(4*w + e, cnt-1)];
                UP[e] = *(const ulonglong2*)(Ub + idx*IDM);
            }
            su_p = __ldg(&gSUb[lst[min(4*w + elane, cnt-1)]]);

            for (int base = 4*w; base < cnt; base += 16) {
                // prefetch next batch before consuming the current one
                ulonglong2 UN[4];
                float su_n = 0.0f;
                int nb = base + 16;
                if (nb < cnt) {
                    #pragma unroll
                    for (int e = 0; e < 4; e++) {
                        int idx = lst[min(nb + e, cnt-1)];
                        UN[e] = *(const ulonglong2*)(Ub + idx*IDM);
                    }
                    su_n = __ldg(&gSUb[lst[min(nb + elane, cnt-1)]]);
                }

                float p[4];
                #pragma unroll
                for (int e = 0; e < 4; e++) {
                    u64 d01 = add2(UP[e].x, nv01);
                    u64 d23 = add2(UP[e].y, nv23);
                    u64 dd01 = mul2(d01, d01), dd23 = mul2(d23, d23);
                    u64 a01 = fma2(dd01, C1_2, C0_2);
                    u64 a23 = fma2(dd23, C1_2, C0_2);
                    u64 g01 = mul2(d01, a01), g23 = mul2(d23, a23);
                    float gx, gy, gz, gw;
                    unpack2(g01, gx, gy); unpack2(g23, gz, gw);
                    float ex = fast_tanh(gx), ey = fast_tanh(gy);
                    float ez = fast_tanh(gz), ew = fast_tanh(gw);
                    u64 e01 = pack2(ex, ey), e23 = pack2(ez, ew);
                    u64 t01 = mul2(d01, w01), t23 = mul2(d23, w23);
                    u64 s2 = fma2(t01, e01, mul2(t23, e23));
                    float slo, shi; unpack2(s2, slo, shi);
                    p[e] = slo + shi;
                }
                // segmented butterfly: 4 sums across 32 lanes in 6 shuffles
                float q0 = (hi4 ? p[2] : p[0]) + __shfl_xor_sync(0xffffffffu, hi4 ? p[0] : p[2], 16);
                float q1 = (hi4 ? p[3] : p[1]) + __shfl_xor_sync(0xffffffffu, hi4 ? p[1] : p[3], 16);
                float s  = (hi3 ? q1 : q0) + __shfl_xor_sync(0xffffffffu, hi3 ? q0 : q1, 8);
                s += __shfl_xor_sync(0xffffffffu, s, 4);
                s += __shfl_xor_sync(0xffffffffu, s, 2);
                s += __shfl_xor_sync(0xffffffffu, s, 1);
                int gidx = base + elane;
                float extra = (gidx < cnt) ? (su_p + cconst) : -3e38f;
                runmax = fmaxf(runmax, s + extra);

                #pragma unroll
                for (int e = 0; e < 4; e++) UP[e] = UN[e];
                su_p = su_n;
            }
            #pragma unroll
            for (int o = 16; o; o >>= 1)
                runmax = fmaxf(runmax, __shfl_xor_sync(0xffffffffu, runmax, o));
        }
        if (lane == 0) pmax_s[w] = runmax;
        __syncthreads();

        // warp 0: node MLP 64->64->1 + sigmoid
        if (w == 0) {
            float nm = fmaxf(fmaxf(pmax_s[0], pmax_s[1]),
                             fmaxf(pmax_s[2], pmax_s[3]));
            float n1a = fmaxf(fmaf(nm, __ldg(&Wn1[lane]),      __ldg(&bn1[lane])),      0.0f);
            float n1b = fmaxf(fmaf(nm, __ldg(&Wn1[lane + 32]), __ldg(&bn1[lane + 32])), 0.0f);
            n1_s[lane]      = n1a;
            n1_s[lane + 32] = n1b;
            __syncwarp();
            float acc0 = __ldg(&bn2[lane]), acc1 = __ldg(&bn2[lane + 32]);
            #pragma unroll 8
            for (int k = 0; k < HD; k++) {
                float f = n1_s[k];
                acc0 = fmaf(f, __ldg(&Wn2[k*HD + lane]),      acc0);
                acc1 = fmaf(f, __ldg(&Wn2[k*HD + lane + 32]), acc1);
            }
            acc0 = fmaxf(acc0, 0.0f);
            acc1 = fmaxf(acc1, 0.0f);
            float part = fmaf(acc0, __ldg(&Wh[lane]), acc1 * __ldg(&Wh[lane + 32]));
            #pragma unroll
            for (int o = 16; o; o >>= 1) part += __shfl_xor_sync(0xffffffffu, part, o);
            if (lane == 0) {
                float lg = part + __ldg(&bh[0]);
                out[g] = 1.0f / (1.0f + expf(-lg));
            }
        }
        __syncthreads();   // protect smem reuse for the second column
    }
}

extern "C" void kernel_launch(void* const* d_in, const int* in_sizes, int n_in,
                              void* d_out, int out_size) {
    const float* bf   = (const float*)d_in[0];
    const float* cls  = (const float*)d_in[1];
    const int*   aid  = (const int*)  d_in[2];
    const float* emb  = (const float*)d_in[3];
    const float* Wcls = (const float*)d_in[4];
    const float* bcls = (const float*)d_in[5];
    const float* Wpos = (const float*)d_in[6];
    const float* bpos = (const float*)d_in[7];
    const float* Win  = (const float*)d_in[8];
    const float* bin  = (const float*)d_in[9];
    const float* Wout = (const float*)d_in[10];
    const float* bout = (const float*)d_in[11];
    const float* We1  = (const float*)d_in[12];
    const float* be1  = (const float*)d_in[13];
    const float* We2  = (const float*)d_in[14];
    const float* be2  = (const float*)d_in[15];
    const float* Wn1  = (const float*)d_in[16];
    const float* bn1  = (const float*)d_in[17];
    const float* Wn2  = (const float*)d_in[18];
    const float* bn2  = (const float*)d_in[19];
    const float* Wh   = (const float*)d_in[20];
    const float* bh   = (const float*)d_in[21];
    float* out = (float*)d_out;

    prep_kernel<<<(BB*NN)/RPB, 128>>>(bf, emb, Wcls, bcls, Wpos, bpos,
                                      Win, bin, Wout, bout, We1, be1, We2);

    // main with PDL: may start while prep drains; syncs in-kernel before
    // reading prep outputs.
    {
        cudaLaunchConfig_t cfg = {};
        cfg.gridDim  = dim3(1024, 1, 1);
        cfg.blockDim = dim3(128, 1, 1);
        cfg.dynamicSmemBytes = 0;
        cfg.stream = 0;
        cudaLaunchAttribute attrs[1];
        attrs[0].id = cudaLaunchAttributeProgrammaticStreamSerialization;
        attrs[0].val.programmaticStreamSerializationAllowed = 1;
        cfg.attrs = attrs;
        cfg.numAttrs = 1;
        cudaLaunchKernelEx(&cfg, main_kernel, cls, aid, emb, We2, be2,
                           Wn1, bn1, Wn2, bn2, Wh, bh, out);
    }
}

// round 17
// speedup vs baseline: 1.2143x; 1.2143x over previous
#include <cuda_runtime.h>
#include <math.h>

#define BB 4
#define NN 512
#define HD 64
#define IDM 128
#define PI_F 3.14159265358979323846f
#define INV_SQRT2 0.70710678118654752440f
#define RPB 8            // rows per prep block

// tanh-based erf approx: erf(d) ~= tanh(C0*d + C1*d^3)
#define ERF_C0 1.1283791671f
#define ERF_C1 0.1009052923f

// Scratch (device globals: no allocation allowed)
__device__ __align__(16) float g_U2[BB*NN*IDM];   // (A@We1 + be1) / sqrt2
__device__ __align__(16) float g_V2[BB*NN*IDM];   // (C@We1)       / sqrt2
__device__ float g_SU[BB*NN];                     // 0.5 * dot(U, w2)
__device__ float g_SV[BB*NN];

typedef unsigned long long u64;

__device__ __forceinline__ u64 pack2(float lo, float hi) {
    u64 r; asm("mov.b64 %0, {%1, %2};" : "=l"(r) : "f"(lo), "f"(hi)); return r;
}
__device__ __forceinline__ void unpack2(u64 v, float& lo, float& hi) {
    asm("mov.b64 {%0, %1}, %2;" : "=f"(lo), "=f"(hi) : "l"(v));
}
__device__ __forceinline__ u64 fma2(u64 a, u64 b, u64 c) {
    u64 r; asm("fma.rn.f32x2 %0, %1, %2, %3;" : "=l"(r) : "l"(a), "l"(b), "l"(c)); return r;
}
__device__ __forceinline__ u64 add2(u64 a, u64 b) {
    u64 r; asm("add.rn.f32x2 %0, %1, %2;" : "=l"(r) : "l"(a), "l"(b)); return r;
}
__device__ __forceinline__ u64 mul2(u64 a, u64 b) {
    u64 r; asm("mul.rn.f32x2 %0, %1, %2;" : "=l"(r) : "l"(a), "l"(b)); return r;
}
__device__ __forceinline__ float fast_tanh(float x) {
    float y; asm("tanh.approx.f32 %0, %1;" : "=f"(y) : "f"(x)); return y;
}

// ---------------------------------------------------------------------------
// Precompute. Grid 256, 128 thr, 8 rows/block. Unroll-8 phases 2/3 (measured
// -1.2 us vs unroll-4 in R16).
// ---------------------------------------------------------------------------
__global__ __launch_bounds__(128) void prep_kernel(
    const float* __restrict__ bf,   const float* __restrict__ emb,
    const float* __restrict__ Wcls, const float* __restrict__ bcls,
    const float* __restrict__ Wpos, const float* __restrict__ bpos,
    const float* __restrict__ Win,  const float* __restrict__ bin,
    const float* __restrict__ Wout, const float* __restrict__ bout,
    const float* __restrict__ We1,  const float* __restrict__ be1,
    const float* __restrict__ We2)
{
    int t = threadIdx.x, lane = t & 31, wid = t >> 5;
    int row0 = blockIdx.x * RPB;

    __shared__ __align__(16) float xs[RPB][HD];
    __shared__ __align__(16) float featsT[HD][RPB];   // k-major
    __shared__ __align__(16) float ApreT[IDM][RPB];   // k-major
    __shared__ __align__(16) float BpreT[IDM][RPB];
    __shared__ float p0s[RPB], p1s[RPB];
    __shared__ float partU[4][RPB], partV[4][RPB];

    for (int idx = t; idx < RPB*HD; idx += 128)
        ((float*)xs)[idx] = bf[row0*HD + idx];

    if (t < RPB) {
        int row = row0 + t;
        float ang = emb[row*2 + 0] * PI_F;
        float rho = emb[row*2 + 1] * 800.0f;
        float tn = tanf(ang);
        float ic = 1.0f / cosf(ang);
        float lin1 = (1.0f - 1e-5f) / 71.0f;
        float y0 = 160.0f;
        float y1 = 160.0f - lin1 * 320.0f;
        p0s[t] = (-tn * y0 + rho * ic) * (1.0f / 800.0f);
        p1s[t] = (-tn * y1 + rho * ic) * (1.0f / 800.0f);
    }
    __syncthreads();

    // phase 1: feats = relu(x @ Wcls + bcls), two rows per pass
    {
        int rhalf = t >> 6, d = t & 63;
        float bc = bcls[d];
        #pragma unroll
        for (int pass = 0; pass < RPB; pass += 2) {
            int r = pass + rhalf;
            float acc = bc;
            #pragma unroll 8
            for (int k = 0; k < HD; k++) acc = fmaf(xs[r][k], Wcls[k*HD + d], acc);
            featsT[d][r] = fmaxf(acc, 0.0f);
        }
    }
    __syncthreads();

    // phase 2: f_in / f_out for all 8 rows (f32x2 packed, unroll 8)
    {
        float bi = bin[t], bo = bout[t];
        u64 ai01 = pack2(bi,bi), ai23 = ai01, ai45 = ai01, ai67 = ai01;
        u64 ao01 = pack2(bo,bo), ao23 = ao01, ao45 = ao01, ao67 = ao01;
        #pragma unroll 8
        for (int k = 0; k < HD; k++) {
            float win  = Win [k*IDM + t];
            float wout = Wout[k*IDM + t];
            u64 wi = pack2(win, win), wo = pack2(wout, wout);
            const ulonglong2* fp = (const ulonglong2*)&featsT[k][0];
            ulonglong2 fA = fp[0], fB = fp[1];
            ai01 = fma2(fA.x, wi, ai01);  ao01 = fma2(fA.x, wo, ao01);
            ai23 = fma2(fA.y, wi, ai23);  ao23 = fma2(fA.y, wo, ao23);
            ai45 = fma2(fB.x, wi, ai45);  ao45 = fma2(fB.x, wo, ao45);
            ai67 = fma2(fB.y, wi, ai67);  ao67 = fma2(fB.y, wo, ao67);
        }
        float wp0 = Wpos[t], wp1 = Wpos[IDM + t], bp = bpos[t];
        float pe[RPB];
        #pragma unroll
        for (int r = 0; r < RPB; r++) pe[r] = fmaf(p0s[r], wp0, p1s[r] * wp1);
        u64 bp2  = pack2(bp, bp);
        u64 pe01 = pack2(pe[0], pe[1]), pe23 = pack2(pe[2], pe[3]);
        u64 pe45 = pack2(pe[4], pe[5]), pe67 = pack2(pe[6], pe[7]);
        u64* arow = (u64*)&ApreT[t][0];
        u64* brow = (u64*)&BpreT[t][0];
        arow[0] = add2(ai01, add2(pe01, bp2));
        arow[1] = add2(ai23, add2(pe23, bp2));
        arow[2] = add2(ai45, add2(pe45, bp2));
        arow[3] = add2(ai67, add2(pe67, bp2));
        brow[0] = add2(ao01, pe01);
        brow[1] = add2(ao23, pe23);
        brow[2] = add2(ao45, pe45);
        brow[3] = add2(ao67, pe67);
    }
    __syncthreads();

    // phase 3: U = Apre @ We1 + be1, V = Bpre @ We1 (f32x2 packed, unroll 8)
    float uu[RPB], vv[RPB];
    {
        float b1 = be1[t];
        u64 u01 = pack2(b1,b1), u23 = u01, u45 = u01, u67 = u01;
        u64 v01 = 0ULL, v23 = 0ULL, v45 = 0ULL, v67 = 0ULL;
        #pragma unroll 8
        for (int k = 0; k < IDM; k++) {
            float w = We1[k*IDM + t];
            u64 w2 = pack2(w, w);
            const ulonglong2* ap = (const ulonglong2*)&ApreT[k][0];
            const ulonglong2* cp = (const ulonglong2*)&BpreT[k][0];
            ulonglong2 aA = ap[0], aB = ap[1];
            ulonglong2 cA = cp[0], cB = cp[1];
            u01 = fma2(aA.x, w2, u01);  v01 = fma2(cA.x, w2, v01);
            u23 = fma2(aA.y, w2, u23);  v23 = fma2(cA.y, w2, v23);
            u45 = fma2(aB.x, w2, u45);  v45 = fma2(cB.x, w2, v45);
            u67 = fma2(aB.y, w2, u67);  v67 = fma2(cB.y, w2, v67);
        }
        u64 is2 = pack2(INV_SQRT2, INV_SQRT2);
        u01 = mul2(u01, is2); u23 = mul2(u23, is2);
        u45 = mul2(u45, is2); u67 = mul2(u67, is2);
        v01 = mul2(v01, is2); v23 = mul2(v23, is2);
        v45 = mul2(v45, is2); v67 = mul2(v67, is2);
        unpack2(u01, uu[0], uu[1]); unpack2(u23, uu[2], uu[3]);
        unpack2(u45, uu[4], uu[5]); unpack2(u67, uu[6], uu[7]);
        unpack2(v01, vv[0], vv[1]); unpack2(v23, vv[2], vv[3]);
        unpack2(v45, vv[4], vv[5]); unpack2(v67, vv[6], vv[7]);
    }

    float w2s = We2[t] * INV_SQRT2;
    #pragma unroll
    for (int r = 0; r < RPB; r++) {
        g_U2[(row0 + r)*IDM + t] = uu[r];
        g_V2[(row0 + r)*IDM + t] = vv[r];
        float su = uu[r] * w2s, sv = vv[r] * w2s;
        #pragma unroll
        for (int o = 16; o; o >>= 1) {
            su += __shfl_xor_sync(0xffffffffu, su, o);
            sv += __shfl_xor_sync(0xffffffffu, sv, o);
        }
        if (lane == 0) { partU[wid][r] = su; partV[wid][r] = sv; }
    }
    __syncthreads();
    if (t < RPB)
        g_SU[row0 + t] = partU[0][t] + partU[1][t] + partU[2][t] + partU[3][t];
    else if (t < 2*RPB) {
        int r = t - RPB;
        g_SV[row0 + r] = partV[0][r] + partV[1][r] + partV[2][r] + partV[3][r];
    }
}

// ---------------------------------------------------------------------------
// Main (exact R13 configuration — measured 21.0 us): ONE column per
// 128-thread block (2048 blocks). PDL: list build (inputs only) overlaps
// prep's tail; grid-dependency sync before touching prep outputs. Merged
// block list, warp-interleaved consumption, batch-4 register double-buffer,
// 6-shuffle segmented reduce.
// ---------------------------------------------------------------------------
__global__ __launch_bounds__(128, 7) void main_kernel(
    const float* __restrict__ cls, const int* __restrict__ aid,
    const float* __restrict__ emb,
    const float* __restrict__ We2, const float* __restrict__ be2,
    const float* __restrict__ Wn1, const float* __restrict__ bn1,
    const float* __restrict__ Wn2, const float* __restrict__ bn2,
    const float* __restrict__ Wh,  const float* __restrict__ bh,
    float* __restrict__ out)
{
    __shared__ unsigned short seg_s[4][128];
    __shared__ unsigned short lst_s[NN];
    __shared__ int cnt_s[4];
    __shared__ float pmax_s[4];
    __shared__ float n1_s[HD];

    int t = threadIdx.x, lane = t & 31, w = t >> 5;
    int g = blockIdx.x;
    int b = g >> 9;

    float cj = __ldg(&cls[g]);
    if (cj < 0.4f) {                   // sigmoid(-1e6) == 0 in f32
#if __CUDA_ARCH__ >= 900
        cudaGridDependencySynchronize();   // keep PDL contract uniform
#endif
        if (t == 0) out[g] = 0.0f;
        return;
    }
    float aj  = __ldg(&emb[2*g]) * PI_F;
    int   idj = __ldg(&aid[g]);

    // per-warp segment list over i in [128w, 128w+128)  (inputs only — pre-sync)
    int cntw = 0;
    {
        unsigned short* seg = seg_s[w];
        int gbase = b*NN + 128*w;
        #pragma unroll
        for (int c = 0; c < 128; c += 32) {
            int gi = gbase + c + lane;
            float ci = __ldg(&cls[gi]);
            float ai = __ldg(&emb[2*gi]) * PI_F;
            int  idi = __ldg(&aid[gi]);
            bool p = (fabsf(ai - aj) < 0.5f) &&
                     ((ci > cj) || ((ci == cj) && (idi > idj)));
            unsigned m = __ballot_sync(0xffffffffu, p);
            if (p) seg[cntw + __popc(m & ((1u << lane) - 1u))]
                       = (unsigned short)(128*w + c + lane);
            cntw += __popc(m);
        }
        if (lane == 0) cnt_s[w] = cntw;
    }
    __syncthreads();

    // merge segments into one contiguous block list
    int c0 = cnt_s[0], c1 = cnt_s[1], c2 = cnt_s[2], c3 = cnt_s[3];
    int cnt = c0 + c1 + c2 + c3;
    {
        int off = (w > 0 ? c0 : 0) + (w > 1 ? c1 : 0) + (w > 2 ? c2 : 0);
        for (int k = lane; k < cntw; k += 32) lst_s[off + k] = seg_s[w][k];
    }

    // wait for prep outputs to be ready (overlapped everything above with prep)
#if __CUDA_ARCH__ >= 900
    cudaGridDependencySynchronize();
#endif
    __syncthreads();

    // per-column constants
    const float* gSUb = g_SU + b*NN;
    ulonglong2 vp = *(const ulonglong2*)(g_V2 + (size_t)g*IDM + lane*4);
    float4 w2r = *(const float4*)(We2 + lane*4);
    float nvx, nvy, nvz, nvw;
    unpack2(vp.x, nvx, nvy); unpack2(vp.y, nvz, nvw);
    u64 nv01 = pack2(-nvx, -nvy), nv23 = pack2(-nvz, -nvw);
    u64 w01 = pack2(w2r.x*INV_SQRT2, w2r.y*INV_SQRT2);
    u64 w23 = pack2(w2r.z*INV_SQRT2, w2r.w*INV_SQRT2);
    u64 C0_2 = pack2(ERF_C0, ERF_C0), C1_2 = pack2(ERF_C1, ERF_C1);
    float cconst = __ldg(&be2[0]) - __ldg(&g_SV[g]);

    const float* Ub = g_U2 + (size_t)b*NN*IDM + lane*4;
    const unsigned short* lst = lst_s;
    // entry-lane mapping for the 4-sum segmented reduce: e = bit3 + 2*bit4
    int elane = ((lane >> 3) & 1) | (((lane >> 4) & 1) << 1);
    bool hi4 = lane & 16, hi3 = lane & 8;

    float runmax = 0.0f;               // diagonal guarantees a 0 entry
    if (4*w < cnt) {
        // warp w consumes batches base = 4w, 4w+16, 4w+32, ...
        ulonglong2 UP[4];
        float su_p;
        #pragma unroll
        for (int e = 0; e < 4; e++) {
            int idx = lst[min(4*w + e, cnt-1)];
            UP[e] = *(const ulonglong2*)(Ub + idx*IDM);
        }
        su_p = __ldg(&gSUb[lst[min(4*w + elane, cnt-1)]]);

        for (int base = 4*w; base < cnt; base += 16) {
            // prefetch next batch before consuming the current one
            ulonglong2 UN[4];
            float su_n = 0.0f;
            int nb = base + 16;
            if (nb < cnt) {
                #pragma unroll
                for (int e = 0; e < 4; e++) {
                    int idx = lst[min(nb + e, cnt-1)];
                    UN[e] = *(const ulonglong2*)(Ub + idx*IDM);
                }
                su_n = __ldg(&gSUb[lst[min(nb + elane, cnt-1)]]);
            }

            float p[4];
            #pragma unroll
            for (int e = 0; e < 4; e++) {
                u64 d01 = add2(UP[e].x, nv01);
                u64 d23 = add2(UP[e].y, nv23);
                u64 dd01 = mul2(d01, d01), dd23 = mul2(d23, d23);
                u64 a01 = fma2(dd01, C1_2, C0_2);
                u64 a23 = fma2(dd23, C1_2, C0_2);
                u64 g01 = mul2(d01, a01), g23 = mul2(d23, a23);
                float gx, gy, gz, gw;
                unpack2(g01, gx, gy); unpack2(g23, gz, gw);
                float ex = fast_tanh(gx), ey = fast_tanh(gy);
                float ez = fast_tanh(gz), ew = fast_tanh(gw);
                u64 e01 = pack2(ex, ey), e23 = pack2(ez, ew);
                u64 t01 = mul2(d01, w01), t23 = mul2(d23, w23);
                u64 s2 = fma2(t01, e01, mul2(t23, e23));
                float slo, shi; unpack2(s2, slo, shi);
                p[e] = slo + shi;
            }
            // segmented butterfly: 4 sums across 32 lanes in 6 shuffles
            float q0 = (hi4 ? p[2] : p[0]) + __shfl_xor_sync(0xffffffffu, hi4 ? p[0] : p[2], 16);
            float q1 = (hi4 ? p[3] : p[1]) + __shfl_xor_sync(0xffffffffu, hi4 ? p[1] : p[3], 16);
            float s  = (hi3 ? q1 : q0) + __shfl_xor_sync(0xffffffffu, hi3 ? q0 : q1, 8);
            s += __shfl_xor_sync(0xffffffffu, s, 4);
            s += __shfl_xor_sync(0xffffffffu, s, 2);
            s += __shfl_xor_sync(0xffffffffu, s, 1);
            int gidx = base + elane;
            float extra = (gidx < cnt) ? (su_p + cconst) : -3e38f;
            runmax = fmaxf(runmax, s + extra);

            #pragma unroll
            for (int e = 0; e < 4; e++) UP[e] = UN[e];
            su_p = su_n;
        }
        #pragma unroll
        for (int o = 16; o; o >>= 1)
            runmax = fmaxf(runmax, __shfl_xor_sync(0xffffffffu, runmax, o));
    }
    if (lane == 0) pmax_s[w] = runmax;
    __syncthreads();

    // warp 0: node MLP 64->64->1 + sigmoid
    if (w == 0) {
        float nm = fmaxf(fmaxf(pmax_s[0], pmax_s[1]),
                         fmaxf(pmax_s[2], pmax_s[3]));
        float n1a = fmaxf(fmaf(nm, __ldg(&Wn1[lane]),      __ldg(&bn1[lane])),      0.0f);
        float n1b = fmaxf(fmaf(nm, __ldg(&Wn1[lane + 32]), __ldg(&bn1[lane + 32])), 0.0f);
        n1_s[lane]      = n1a;
        n1_s[lane + 32] = n1b;
        __syncwarp();
        float acc0 = __ldg(&bn2[lane]), acc1 = __ldg(&bn2[lane + 32]);
        #pragma unroll 8
        for (int k = 0; k < HD; k++) {
            float f = n1_s[k];
            acc0 = fmaf(f, __ldg(&Wn2[k*HD + lane]),      acc0);
            acc1 = fmaf(f, __ldg(&Wn2[k*HD + lane + 32]), acc1);
        }
        acc0 = fmaxf(acc0, 0.0f);
        acc1 = fmaxf(acc1, 0.0f);
        float part = fmaf(acc0, __ldg(&Wh[lane]), acc1 * __ldg(&Wh[lane + 32]));
        #pragma unroll
        for (int o = 16; o; o >>= 1) part += __shfl_xor_sync(0xffffffffu, part, o);
        if (lane == 0) {
            float lg = part + __ldg(&bh[0]);
            out[g] = 1.0f / (1.0f + expf(-lg));
        }
    }
}

extern "C" void kernel_launch(void* const* d_in, const int* in_sizes, int n_in,
                              void* d_out, int out_size) {
    const float* bf   = (const float*)d_in[0];
    const float* cls  = (const float*)d_in[1];
    const int*   aid  = (const int*)  d_in[2];
    const float* emb  = (const float*)d_in[3];
    const float* Wcls = (const float*)d_in[4];
    const float* bcls = (const float*)d_in[5];
    const float* Wpos = (const float*)d_in[6];
    const float* bpos = (const float*)d_in[7];
    const float* Win  = (const float*)d_in[8];
    const float* bin  = (const float*)d_in[9];
    const float* Wout = (const float*)d_in[10];
    const float* bout = (const float*)d_in[11];
    const float* We1  = (const float*)d_in[12];
    const float* be1  = (const float*)d_in[13];
    const float* We2  = (const float*)d_in[14];
    const float* be2  = (const float*)d_in[15];
    const float* Wn1  = (const float*)d_in[16];
    const float* bn1  = (const float*)d_in[17];
    const float* Wn2  = (const float*)d_in[18];
    const float* bn2  = (const float*)d_in[19];
    const float* Wh   = (const float*)d_in[20];
    const float* bh   = (const float*)d_in[21];
    float* out = (float*)d_out;

    prep_kernel<<<(BB*NN)/RPB, 128>>>(bf, emb, Wcls, bcls, Wpos, bpos,
                                      Win, bin, Wout, bout, We1, be1, We2);

    // main with PDL: may start while prep drains; syncs in-kernel before
    // reading prep outputs.
    {
        cudaLaunchConfig_t cfg = {};
        cfg.gridDim  = dim3(BB*NN, 1, 1);
        cfg.blockDim = dim3(128, 1, 1);
        cfg.dynamicSmemBytes = 0;
        cfg.stream = 0;
        cudaLaunchAttribute attrs[1];
        attrs[0].id = cudaLaunchAttributeProgrammaticStreamSerialization;
        attrs[0].val.programmaticStreamSerializationAllowed = 1;
        cfg.attrs = attrs;
        cfg.numAttrs = 1;
        cudaLaunchKernelEx(&cfg, main_kernel, cls, aid, emb, We2, be2,
                           Wn1, bn1, Wn2, bn2, Wh, bh, out);
    }
}